// round 7
// baseline (speedup 1.0000x reference)
#include <cuda_runtime.h>
#include <math.h>

#define BB    4
#define SSEQ  4096
#define IND   1024
#define OUTD  1024
#define EE    8
#define LSCALE 512.0f

// ---- scratch (device globals; allocation is forbidden) ----
__device__ float g_seg[BB * IND];               // 16 KB : per-batch column sums of x
__device__ float g_h[(size_t)BB * SSEQ * EE];   // 512 KB: all-expert dots (L2 resident)
__device__ float g_coef[BB * 2];
__device__ int   g_idx[BB * 2];

typedef unsigned long long u64;

__device__ __forceinline__ void fma2(u64& d, u64 a, u64 b) {
    asm("fma.rn.f32x2 %0, %1, %2, %0;" : "+l"(d) : "l"(a), "l"(b));
}
__device__ __forceinline__ float lo2(u64 v) { return __uint_as_float((unsigned)(v & 0xffffffffull)); }
__device__ __forceinline__ float hi2(u64 v) { return __uint_as_float((unsigned)(v >> 32)); }

// ------------------------------------------------------------------
// K1: h[b,s,e] = x[b,s,:]·A_e (8 experts) + per-batch column sums.
// 512 blocks (32 tokens), 256 thr, 2 CTAs/SM.
// cp.async 3-stage pipeline: chunk c+3 prefetches into shared while
// chunk c computes FROM shared -> DRAM latency decoupled from both
// registers and warp count. A in shared as [e][k] float (LDS.128,
// conflict-free). Seg partials: 4 REDG per warp-chunk.
// ------------------------------------------------------------------
#define TPW   4
#define TOKB  32
#define NST   3
#define STAGE 4096      // floats per stage: 32 tokens x 128

extern __shared__ float s_dyn[];

__device__ __forceinline__ void copy_stage(float* dst, const float* xbase,
                                           int c, int tid) {
    unsigned dbase = (unsigned)__cvta_generic_to_shared(dst);
    #pragma unroll
    for (int j = 0; j < 4; ++j) {
        int u   = tid + j * 256;              // 0..1023 float4 units
        int row = u >> 5;
        int col = (u & 31) * 4;
        const float* src = xbase + (size_t)row * IND + c * 128 + col;
        unsigned daddr = dbase + (unsigned)((row * 128 + col) * 4);
        asm volatile("cp.async.cg.shared.global [%0], [%1], 16;\n"
                     :: "r"(daddr), "l"(src));
    }
}

__global__ void __launch_bounds__(256, 2) k1_dots(const float* __restrict__ x,
                                                  const float* __restrict__ lora_A) {
    float* A_s = s_dyn;             // 8192 floats (32 KB) : [e][1024]
    float* xst = s_dyn + 8192;      // 3 * 4096 floats (48 KB)

    const int tid  = threadIdx.x;
    const int w    = tid >> 5;
    const int lane = tid & 31;
    const int b       = blockIdx.x >> 7;           // 128 blocks per batch
    const int tokbase = (blockIdx.x & 127) * TOKB;
    const float* xbase = x + ((size_t)b * SSEQ + tokbase) * IND;

    // stage A once (coalesced float4 copy)
    #pragma unroll
    for (int j = 0; j < 8; ++j)
        ((float4*)A_s)[tid + j * 256] = ((const float4*)lora_A)[tid + j * 256];

    // pipeline prologue: chunks 0..2 in flight
    #pragma unroll
    for (int c = 0; c < NST; ++c) {
        copy_stage(xst + c * STAGE, xbase, c, tid);
        asm volatile("cp.async.commit_group;");
    }

    u64 acc[TPW][EE];
    #pragma unroll
    for (int t = 0; t < TPW; ++t)
        #pragma unroll
        for (int e = 0; e < EE; ++e) acc[t][e] = 0ull;

    #pragma unroll 1
    for (int c = 0; c < 8; ++c) {
        asm volatile("cp.async.wait_group 2;");
        __syncthreads();                           // stage c (and A at c=0) visible

        const float* xs = xst + (c % NST) * STAGE + (w * TPW) * 128 + lane * 4;

        // x for this warp's 4 tokens from shared (LDS.128, conflict-free)
        u64 xlo[TPW], xhi[TPW];
        #pragma unroll
        for (int t = 0; t < TPW; ++t) {
            double2 xv = *(const double2*)(xs + t * 128);
            xlo[t] = __double_as_longlong(xv.x);
            xhi[t] = __double_as_longlong(xv.y);
        }

        // seg partial -> REDG (spread addresses, no return)
        {
            float sx = 0.f, sy = 0.f, sz = 0.f, sw = 0.f;
            #pragma unroll
            for (int t = 0; t < TPW; ++t) {
                sx += lo2(xlo[t]); sy += hi2(xlo[t]);
                sz += lo2(xhi[t]); sw += hi2(xhi[t]);
            }
            float* dst = &g_seg[b * IND + c * 128 + lane * 4];
            atomicAdd(dst + 0, sx);
            atomicAdd(dst + 1, sy);
            atomicAdd(dst + 2, sz);
            atomicAdd(dst + 3, sw);
        }

        // 8 experts: one conflict-free LDS.128 each, k-paired FMA2s
        #pragma unroll
        for (int e = 0; e < EE; ++e) {
            double2 av = *(const double2*)&A_s[e * IND + c * 128 + lane * 4];
            u64 alo = __double_as_longlong(av.x);
            u64 ahi = __double_as_longlong(av.y);
            #pragma unroll
            for (int t = 0; t < TPW; ++t) {
                fma2(acc[t][e], xlo[t], alo);
                fma2(acc[t][e], xhi[t], ahi);
            }
        }

        __syncthreads();                           // all warps done with stage c
        if (c + NST < 8)
            copy_stage(xst + (c % NST) * STAGE, xbase, c + NST, tid);
        asm volatile("cp.async.commit_group;");    // (possibly empty) keep count
    }

    // ---- per-token cross-lane reduction + h store ----
    #pragma unroll
    for (int i = 0; i < TPW; ++i) {
        float v[EE];
        #pragma unroll
        for (int e = 0; e < EE; ++e) v[e] = lo2(acc[i][e]) + hi2(acc[i][e]);
        #pragma unroll
        for (int off = 16; off; off >>= 1)
            #pragma unroll
            for (int e = 0; e < EE; ++e)
                v[e] += __shfl_xor_sync(0xffffffffu, v[e], off);
        if (lane == 0) {
            size_t gt = (size_t)b * SSEQ + tokbase + w * TPW + i;
            *(float4*)&g_h[gt * EE]     = make_float4(v[0], v[1], v[2], v[3]);
            *(float4*)&g_h[gt * EE + 4] = make_float4(v[4], v[5], v[6], v[7]);
        }
    }
}

// ------------------------------------------------------------------
// K2: logits = seg_mean·G^T + b ; softmax ; top-2 ; coef = 512*w.
// Also re-zeroes g_seg for the next graph replay.
// ------------------------------------------------------------------
__global__ void k2_gate(const float* __restrict__ gate_w,
                        const float* __restrict__ gate_b) {
    __shared__ float dots[BB * EE];
    int tid = threadIdx.x;                  // 1024 threads
    int pair = tid >> 5, lane = tid & 31;   // 32 (b,e) pairs, one warp each
    int b = pair >> 3, e = pair & 7;

    float s = 0.f;
    for (int k = lane * 4; k < IND; k += 128) {
        float4 a = *(const float4*)&g_seg[b * IND + k];
        float4 g = *(const float4*)&gate_w[e * IND + k];
        s += a.x * g.x + a.y * g.y + a.z * g.z + a.w * g.w;
    }
    #pragma unroll
    for (int o = 16; o; o >>= 1) s += __shfl_xor_sync(0xffffffffu, s, o);
    if (lane == 0) dots[pair] = s * (1.0f / (float)SSEQ) + gate_b[e];
    __syncthreads();

    // zero g_seg for next replay (4096 floats = 1024 float4)
    ((float4*)g_seg)[tid] = make_float4(0.f, 0.f, 0.f, 0.f);

    if (tid < BB) {
        int bb = tid;
        float l[EE]; float mx = -1e30f;
        #pragma unroll
        for (int i = 0; i < EE; ++i) { l[i] = dots[bb * EE + i]; mx = fmaxf(mx, l[i]); }
        float sum = 0.f;
        #pragma unroll
        for (int i = 0; i < EE; ++i) { l[i] = expf(l[i] - mx); sum += l[i]; }
        int i0 = 0;
        #pragma unroll
        for (int i = 1; i < EE; ++i) if (l[i] > l[i0]) i0 = i;     // ties -> lowest idx
        int i1 = (i0 == 0) ? 1 : 0;
        #pragma unroll
        for (int i = 0; i < EE; ++i) if (i != i0 && l[i] > l[i1]) i1 = i;
        g_idx[bb * 2] = i0;  g_idx[bb * 2 + 1] = i1;
        float f = LSCALE / sum;
        g_coef[bb * 2]     = l[i0] * f;
        g_coef[bb * 2 + 1] = l[i1] * f;
    }
}

// ------------------------------------------------------------------
// K3: out[b,s,:] = c0*B_{e0} + c1*B_{e1}. Warp owns 2 tokens; B rows
// register-resident per lane; coefs via broadcast LDG; coalesced
// STG.128. grid 1024 for even wave balance.
// ------------------------------------------------------------------
#define TC3 16
__global__ void __launch_bounds__(256) k3_out(const float* __restrict__ lora_B,
                                              float* __restrict__ out) {
    const int tid = threadIdx.x;
    const int w = tid >> 5, lane = tid & 31;
    const int b = blockIdx.x >> 8;                 // 256 blocks per batch
    const int tokbase = (blockIdx.x & 255) * TC3;
    const int e0 = g_idx[b * 2], e1 = g_idx[b * 2 + 1];
    const float w0 = g_coef[b * 2], w1 = g_coef[b * 2 + 1];

    float4 B0r[8], B1r[8];
    #pragma unroll
    for (int j = 0; j < 8; ++j) {
        B0r[j] = *(const float4*)&lora_B[e0 * OUTD + j * 128 + lane * 4];
        B1r[j] = *(const float4*)&lora_B[e1 * OUTD + j * 128 + lane * 4];
    }

    #pragma unroll
    for (int t = 0; t < 2; ++t) {
        size_t gt = (size_t)b * SSEQ + tokbase + w * 2 + t;
        float c0 = w0 * __ldg(&g_h[gt * EE + e0]);   // broadcast (same addr per warp)
        float c1 = w1 * __ldg(&g_h[gt * EE + e1]);
        float4* orow = (float4*)out + gt * (OUTD / 4) + lane;
        #pragma unroll
        for (int j = 0; j < 8; ++j) {
            float4 v;
            v.x = c0 * B0r[j].x + c1 * B1r[j].x;
            v.y = c0 * B0r[j].y + c1 * B1r[j].y;
            v.z = c0 * B0r[j].z + c1 * B1r[j].z;
            v.w = c0 * B0r[j].w + c1 * B1r[j].w;
            orow[j * 32] = v;
        }
    }
}

// ------------------------------------------------------------------
extern "C" void kernel_launch(void* const* d_in, const int* in_sizes, int n_in,
                              void* d_out, int out_size) {
    const float* x      = (const float*)d_in[0];
    const float* lora_A = (const float*)d_in[1];
    const float* lora_B = (const float*)d_in[2];
    const float* gate_w = (const float*)d_in[3];
    const float* gate_b = (const float*)d_in[4];
    float* out = (float*)d_out;

    static bool attr_set = false;
    if (!attr_set) {
        cudaFuncSetAttribute(k1_dots, cudaFuncAttributeMaxDynamicSharedMemorySize, 81920);
        attr_set = true;
    }

    k1_dots<<<BB * (SSEQ / TOKB), 256, 81920>>>(x, lora_A);
    k2_gate<<<1, 1024>>>(gate_w, gate_b);
    k3_out<<<BB * (SSEQ / TC3), 256>>>(lora_B, out);
}

// round 8
// speedup vs baseline: 2.4933x; 2.4933x over previous
#include <cuda_runtime.h>
#include <math.h>

#define BB    4
#define SSEQ  4096
#define IND   1024
#define OUTD  1024
#define EE    8
#define LSCALE 512.0f

// ---- scratch (device globals; allocation is forbidden) ----
__device__ float    g_seg[BB * IND];               // 16 KB : per-batch column sums
__device__ float    g_h[(size_t)BB * SSEQ * EE];   // 512 KB: all-expert dots
__device__ float    g_coef[BB * 2];
__device__ int      g_idx[BB * 2];
__device__ unsigned g_arrive;                      // k1 completion counter (reset each run)

typedef unsigned long long u64;

__device__ __forceinline__ void fma2(u64& d, u64 a, u64 b) {
    asm("fma.rn.f32x2 %0, %1, %2, %0;" : "+l"(d) : "l"(a), "l"(b));
}
__device__ __forceinline__ float lo2(u64 v) { return __uint_as_float((unsigned)(v & 0xffffffffull)); }
__device__ __forceinline__ float hi2(u64 v) { return __uint_as_float((unsigned)(v >> 32)); }

// streaming 16B load (evict-first: x is read exactly once)
__device__ __forceinline__ void ldcs2(const float* p, u64& lo, u64& hi) {
    asm("ld.global.cs.v2.u64 {%0, %1}, [%2];" : "=l"(lo), "=l"(hi) : "l"(p));
}
// streaming 16B store (out is never re-read)
__device__ __forceinline__ void stcs4(float* p, float4 v) {
    asm volatile("st.global.cs.v4.f32 [%0], {%1, %2, %3, %4};"
                 :: "l"(p), "f"(v.x), "f"(v.y), "f"(v.z), "f"(v.w));
}

// ------------------------------------------------------------------
// K1 (round-2 proven config): h[b,s,e] = x[b,s,:]·A_e + seg sums,
// PLUS fused gating in the last CTA to finish (replaces k2).
// grid=512 (32 tokens/blk), 256 thr, 64KB smem, 2 CTAs/SM.
// ------------------------------------------------------------------
#define TPW  4
#define TOKB 32

extern __shared__ float s_dyn[];

__global__ void __launch_bounds__(256, 2) k1_dots(const float* __restrict__ x,
                                                  const float* __restrict__ lora_A,
                                                  const float* __restrict__ gate_w,
                                                  const float* __restrict__ gate_b) {
    float* A_s  = s_dyn;          // 32 KB : [e][1024]
    float* segp = s_dyn + 8192;   // 32 KB : [warp][1024]

    const int tid  = threadIdx.x;
    const int w    = tid >> 5;
    const int lane = tid & 31;
    const int b       = blockIdx.x >> 7;            // 128 blocks per batch
    const int tokbase = (blockIdx.x & 127) * TOKB;

    // stage A once (pure float4 copy, coalesced, conflict-free)
    #pragma unroll
    for (int j = 0; j < 8; ++j) {
        int i4 = tid + j * 256;
        ((float4*)A_s)[i4] = ((const float4*)lora_A)[i4];
    }
    __syncthreads();

    u64 acc[TPW][EE];
    #pragma unroll
    for (int i = 0; i < TPW; ++i)
        #pragma unroll
        for (int e = 0; e < EE; ++e) acc[i][e] = 0ull;

    const float* xw = x + ((size_t)(b * SSEQ + tokbase + w * TPW)) * IND;

    #pragma unroll
    for (int c = 0; c < 8; ++c) {                   // 8 k-chunks of 128
        const int cc   = (c + w) & 7;               // warp-staggered chunk order
        const int koff = cc * 128 + lane * 4;

        // x for this warp's 4 tokens (streaming LDG.128)
        u64 xlo[TPW], xhi[TPW];
        #pragma unroll
        for (int t = 0; t < TPW; ++t)
            ldcs2(xw + (size_t)t * IND + koff, xlo[t], xhi[t]);

        // seg partial: each (warp,chunk,lane) slot written exactly once
        {
            float4 s = make_float4(0.f, 0.f, 0.f, 0.f);
            #pragma unroll
            for (int t = 0; t < TPW; ++t) {
                s.x += lo2(xlo[t]); s.y += hi2(xlo[t]);
                s.z += lo2(xhi[t]); s.w += hi2(xhi[t]);
            }
            *(float4*)&segp[w * IND + koff] = s;
        }

        // 8 experts; A as LDS.128 (conflict-free), k-paired packed FMAs
        #pragma unroll
        for (int e = 0; e < EE; ++e) {
            double2 av = *(const double2*)&A_s[e * IND + koff];
            u64 alo = __double_as_longlong(av.x);
            u64 ahi = __double_as_longlong(av.y);
            #pragma unroll
            for (int t = 0; t < TPW; ++t) {
                fma2(acc[t][e], xlo[t], alo);
                fma2(acc[t][e], xhi[t], ahi);
            }
        }
    }

    // ---- per-token cross-lane reduction + h store ----
    #pragma unroll
    for (int i = 0; i < TPW; ++i) {
        float v[EE];
        #pragma unroll
        for (int e = 0; e < EE; ++e) v[e] = lo2(acc[i][e]) + hi2(acc[i][e]);
        #pragma unroll
        for (int off = 16; off; off >>= 1)
            #pragma unroll
            for (int e = 0; e < EE; ++e)
                v[e] += __shfl_xor_sync(0xffffffffu, v[e], off);
        if (lane == 0) {
            size_t gt = (size_t)b * SSEQ + tokbase + w * TPW + i;
            *(float4*)&g_h[gt * EE]     = make_float4(v[0], v[1], v[2], v[3]);
            *(float4*)&g_h[gt * EE + 4] = make_float4(v[4], v[5], v[6], v[7]);
        }
    }

    // ---- cross-warp seg reduction + REDG ----
    __syncthreads();
    {
        float4 s = ((float4*)segp)[tid];
        #pragma unroll
        for (int ww = 1; ww < 8; ++ww) {
            float4 t = *(float4*)&segp[ww * IND + tid * 4];
            s.x += t.x; s.y += t.y; s.z += t.z; s.w += t.w;
        }
        float* dst = &g_seg[b * IND + tid * 4];
        atomicAdd(dst + 0, s.x);
        atomicAdd(dst + 1, s.y);
        atomicAdd(dst + 2, s.z);
        atomicAdd(dst + 3, s.w);
    }

    // ================= fused gating: last CTA to finish =================
    __threadfence();
    __shared__ unsigned s_last;
    if (tid == 0)
        s_last = (atomicAdd(&g_arrive, 1u) == (unsigned)(gridDim.x - 1)) ? 1u : 0u;
    __syncthreads();
    if (!s_last) return;
    __threadfence();                                // acquire: g_seg fully visible

    __shared__ float dots[BB * EE];
    {
        // 32 (b,e) pairs x 8 threads each
        int pair = tid >> 3, l8 = tid & 7;
        int bb = pair >> 3, e = pair & 7;
        float s = 0.f;
        #pragma unroll 8
        for (int k = l8 * 4; k < IND; k += 32) {
            float4 a = *(const float4*)&g_seg[bb * IND + k];
            float4 g = *(const float4*)&gate_w[e * IND + k];
            s += a.x * g.x + a.y * g.y + a.z * g.z + a.w * g.w;
        }
        #pragma unroll
        for (int o = 4; o; o >>= 1) s += __shfl_xor_sync(0xffffffffu, s, o);
        if (l8 == 0) dots[pair] = s * (1.0f / (float)SSEQ) + gate_b[e];
    }
    __syncthreads();

    // zero g_seg for next replay (4096 floats = 1024 float4, 4 per thread)
    #pragma unroll
    for (int j = 0; j < 4; ++j)
        ((float4*)g_seg)[tid + j * 256] = make_float4(0.f, 0.f, 0.f, 0.f);

    if (tid < BB) {
        int bb = tid;
        float l[EE]; float mx = -1e30f;
        #pragma unroll
        for (int i = 0; i < EE; ++i) { l[i] = dots[bb * EE + i]; mx = fmaxf(mx, l[i]); }
        float sum = 0.f;
        #pragma unroll
        for (int i = 0; i < EE; ++i) { l[i] = expf(l[i] - mx); sum += l[i]; }
        int i0 = 0;
        #pragma unroll
        for (int i = 1; i < EE; ++i) if (l[i] > l[i0]) i0 = i;     // ties -> lowest idx
        int i1 = (i0 == 0) ? 1 : 0;
        #pragma unroll
        for (int i = 0; i < EE; ++i) if (i != i0 && l[i] > l[i1]) i1 = i;
        g_idx[bb * 2] = i0;  g_idx[bb * 2 + 1] = i1;
        float f = LSCALE / sum;
        g_coef[bb * 2]     = l[i0] * f;
        g_coef[bb * 2 + 1] = l[i1] * f;
    }
    if (tid == 0) g_arrive = 0;                     // reset for next graph replay
}

// ------------------------------------------------------------------
// K3 (round-1 measured-best shape): out = c0*B_{e0} + c1*B_{e1}.
// TC=32 tokens/block, grid 512, B register-resident (2 float4/thr),
// unroll 4, streaming STG.128.
// ------------------------------------------------------------------
#define TC 32
__global__ void __launch_bounds__(256) k3_out(const float* __restrict__ lora_B,
                                              float* __restrict__ out) {
    __shared__ float2 cs[TC];
    const int tid = threadIdx.x;
    const int b = blockIdx.x >> 7;                 // 128 blocks per batch
    const int tokbase = (blockIdx.x & 127) * TC;
    const int e0 = g_idx[b * 2], e1 = g_idx[b * 2 + 1];
    const float w0 = g_coef[b * 2], w1 = g_coef[b * 2 + 1];

    if (tid < TC) {
        size_t gt = (size_t)b * SSEQ + tokbase + tid;
        cs[tid] = make_float2(w0 * g_h[gt * EE + e0], w1 * g_h[gt * EE + e1]);
    }
    float4 B0 = *(const float4*)&lora_B[e0 * OUTD + tid * 4];
    float4 B1 = *(const float4*)&lora_B[e1 * OUTD + tid * 4];
    __syncthreads();

    float* ob = out + ((size_t)b * SSEQ + tokbase) * OUTD + tid * 4;
    #pragma unroll 4
    for (int i = 0; i < TC; ++i) {
        float2 cc = cs[i];
        float4 v;
        v.x = cc.x * B0.x + cc.y * B1.x;
        v.y = cc.x * B0.y + cc.y * B1.y;
        v.z = cc.x * B0.z + cc.y * B1.z;
        v.w = cc.x * B0.w + cc.y * B1.w;
        stcs4(ob + (size_t)i * OUTD, v);
    }
}

// ------------------------------------------------------------------
extern "C" void kernel_launch(void* const* d_in, const int* in_sizes, int n_in,
                              void* d_out, int out_size) {
    const float* x      = (const float*)d_in[0];
    const float* lora_A = (const float*)d_in[1];
    const float* lora_B = (const float*)d_in[2];
    const float* gate_w = (const float*)d_in[3];
    const float* gate_b = (const float*)d_in[4];
    float* out = (float*)d_out;

    static bool attr_set = false;
    if (!attr_set) {
        cudaFuncSetAttribute(k1_dots, cudaFuncAttributeMaxDynamicSharedMemorySize, 65536);
        attr_set = true;
    }

    k1_dots<<<BB * (SSEQ / TOKB), 256, 65536>>>(x, lora_A, gate_w, gate_b);
    k3_out<<<BB * (SSEQ / TC), 256>>>(lora_B, out);
}

// round 9
// speedup vs baseline: 2.6053x; 1.0449x over previous
#include <cuda_runtime.h>
#include <math.h>

#define BB    4
#define SSEQ  4096
#define IND   1024
#define OUTD  1024
#define EE    8
#define LSCALE 512.0f

// ---- scratch (device globals; allocation is forbidden) ----
__device__ float    g_seg[BB * IND];               // 16 KB : per-batch column sums
__device__ float    g_h[(size_t)BB * SSEQ * EE];   // 512 KB: all-expert dots
__device__ float    g_coef[BB * 2];
__device__ int      g_idx[BB * 2];
__device__ unsigned g_arrive;                      // k1 completion counter

typedef unsigned long long u64;

__device__ __forceinline__ void fma2(u64& d, u64 a, u64 b) {
    asm("fma.rn.f32x2 %0, %1, %2, %0;" : "+l"(d) : "l"(a), "l"(b));
}
__device__ __forceinline__ void add2(u64& d, u64 a) {
    asm("add.rn.f32x2 %0, %0, %1;" : "+l"(d) : "l"(a));
}
__device__ __forceinline__ float lo2(u64 v) { return __uint_as_float((unsigned)(v & 0xffffffffull)); }
__device__ __forceinline__ float hi2(u64 v) { return __uint_as_float((unsigned)(v >> 32)); }

// streaming 16B store (out is never re-read)
__device__ __forceinline__ void stcs4(float* p, float4 v) {
    asm volatile("st.global.cs.v4.f32 [%0], {%1, %2, %3, %4};"
                 :: "l"(p), "f"(v.x), "f"(v.y), "f"(v.z), "f"(v.w));
}

// ------------------------------------------------------------------
// K1: EXACT round-2 hot loop (measured 22.9us) + fused gating tail.
// grid = 512 blocks (128/batch, 32 tokens each), 256 threads.
// Warp owns 4 tokens; lane owns 4 consecutive k per 128-chunk.
// x: direct coalesced LDG.128 (plain, no .cs, no stagger).
// A: staged once to shared [e][k]; packed f32x2 FMAs over k-pairs.
// ------------------------------------------------------------------
#define TPW  4      // tokens per warp
#define TOKB 32     // tokens per block

extern __shared__ float s_dyn[];

__global__ void __launch_bounds__(256, 2) k1_dots(const float* __restrict__ x,
                                                  const float* __restrict__ lora_A,
                                                  const float* __restrict__ gate_w,
                                                  const float* __restrict__ gate_b) {
    float* A_s  = s_dyn;          // 8192 floats (32 KB), [e][1024]
    float* segp = s_dyn + 8192;   // 8192 floats (32 KB), [warp][1024]

    const int tid  = threadIdx.x;
    const int w    = tid >> 5;
    const int lane = tid & 31;
    const int b       = blockIdx.x >> 7;           // 128 blocks per batch
    const int tokbase = (blockIdx.x & 127) * TOKB;

    // stage A once (contiguous copy, conflict-free)
    #pragma unroll
    for (int j = 0; j < 8; ++j) {
        int i4 = tid + j * 256;                    // 2048 float4 total
        ((float4*)A_s)[i4] = ((const float4*)lora_A)[i4];
    }
    __syncthreads();

    u64 acc[TPW][EE];
    #pragma unroll
    for (int i = 0; i < TPW; ++i)
        #pragma unroll
        for (int e = 0; e < EE; ++e) acc[i][e] = 0ull;

    const float* xw = x + ((size_t)(b * SSEQ + tokbase + w * TPW)) * IND;

    #pragma unroll
    for (int c = 0; c < 8; ++c) {                  // 8 k-chunks of 128
        const int koff = c * 128 + lane * 4;

        // x for this warp's 4 tokens (coalesced LDG.128)
        u64 xlo[TPW], xhi[TPW];
        u64 seglo = 0ull, seghi = 0ull;
        #pragma unroll
        for (int i = 0; i < TPW; ++i) {
            double2 xv = *(const double2*)(xw + (size_t)i * IND + koff);
            xlo[i] = __double_as_longlong(xv.x);
            xhi[i] = __double_as_longlong(xv.y);
            add2(seglo, xlo[i]);
            add2(seghi, xhi[i]);
        }

        // 8 experts, A float4 from shared (conflict-free, 2 live regs)
        #pragma unroll
        for (int e = 0; e < EE; ++e) {
            double2 av = *(const double2*)&A_s[e * IND + koff];
            u64 alo = __double_as_longlong(av.x);
            u64 ahi = __double_as_longlong(av.y);
            #pragma unroll
            for (int i = 0; i < TPW; ++i) {
                fma2(acc[i][e], xlo[i], alo);
                fma2(acc[i][e], xhi[i], ahi);
            }
        }

        // flush this chunk's seg partial (each slot written exactly once)
        double2 sv;
        sv.x = __longlong_as_double(seglo);
        sv.y = __longlong_as_double(seghi);
        *(double2*)&segp[w * IND + koff] = sv;
    }

    // ---- per-token cross-lane reduction (butterfly) + h store ----
    #pragma unroll
    for (int i = 0; i < TPW; ++i) {
        float v[EE];
        #pragma unroll
        for (int e = 0; e < EE; ++e) v[e] = lo2(acc[i][e]) + hi2(acc[i][e]);
        #pragma unroll
        for (int off = 16; off; off >>= 1)
            #pragma unroll
            for (int e = 0; e < EE; ++e)
                v[e] += __shfl_xor_sync(0xffffffffu, v[e], off);
        if (lane == 0) {
            size_t gt = (size_t)b * SSEQ + tokbase + w * TPW + i;
            *(float4*)&g_h[gt * EE]     = make_float4(v[0], v[1], v[2], v[3]);
            *(float4*)&g_h[gt * EE + 4] = make_float4(v[4], v[5], v[6], v[7]);
        }
    }

    // ---- cross-warp seg reduction + REDG ----
    __syncthreads();
    {
        float4 s = ((float4*)segp)[tid];           // warp 0's row
        #pragma unroll
        for (int ww = 1; ww < 8; ++ww) {
            float4 t = *(float4*)&segp[ww * IND + tid * 4];
            s.x += t.x; s.y += t.y; s.z += t.z; s.w += t.w;
        }
        float* dst = &g_seg[b * IND + tid * 4];
        atomicAdd(dst + 0, s.x);
        atomicAdd(dst + 1, s.y);
        atomicAdd(dst + 2, s.z);
        atomicAdd(dst + 3, s.w);
    }

    // ================= fused gating: last CTA to finish =================
    __threadfence();
    __shared__ unsigned s_last;
    if (tid == 0)
        s_last = (atomicAdd(&g_arrive, 1u) == (unsigned)(gridDim.x - 1)) ? 1u : 0u;
    __syncthreads();
    if (!s_last) return;
    __threadfence();                               // acquire: g_seg fully visible

    __shared__ float dots[BB * EE];
    {
        int pair = tid >> 3, l8 = tid & 7;         // 32 (b,e) pairs x 8 threads
        int bb = pair >> 3, e = pair & 7;
        float s = 0.f;
        #pragma unroll 8
        for (int k = l8 * 4; k < IND; k += 32) {
            float4 a = *(const float4*)&g_seg[bb * IND + k];
            float4 g = *(const float4*)&gate_w[e * IND + k];
            s += a.x * g.x + a.y * g.y + a.z * g.z + a.w * g.w;
        }
        #pragma unroll
        for (int o = 4; o; o >>= 1) s += __shfl_xor_sync(0xffffffffu, s, o);
        if (l8 == 0) dots[pair] = s * (1.0f / (float)SSEQ) + gate_b[e];
    }
    __syncthreads();

    // zero g_seg for next replay (1024 float4, 4 per thread)
    #pragma unroll
    for (int j = 0; j < 4; ++j)
        ((float4*)g_seg)[tid + j * 256] = make_float4(0.f, 0.f, 0.f, 0.f);

    if (tid < BB) {
        int bb = tid;
        float l[EE]; float mx = -1e30f;
        #pragma unroll
        for (int i = 0; i < EE; ++i) { l[i] = dots[bb * EE + i]; mx = fmaxf(mx, l[i]); }
        float sum = 0.f;
        #pragma unroll
        for (int i = 0; i < EE; ++i) { l[i] = expf(l[i] - mx); sum += l[i]; }
        int i0 = 0;
        #pragma unroll
        for (int i = 1; i < EE; ++i) if (l[i] > l[i0]) i0 = i;     // ties -> lowest idx
        int i1 = (i0 == 0) ? 1 : 0;
        #pragma unroll
        for (int i = 0; i < EE; ++i) if (i != i0 && l[i] > l[i1]) i1 = i;
        g_idx[bb * 2] = i0;  g_idx[bb * 2 + 1] = i1;
        float f = LSCALE / sum;
        g_coef[bb * 2]     = l[i0] * f;
        g_coef[bb * 2 + 1] = l[i1] * f;
    }
    if (tid == 0) g_arrive = 0;                    // reset for next graph replay
}

// ------------------------------------------------------------------
// K3 (round-8 measured best, 13.9us): out = c0*B_{e0} + c1*B_{e1}.
// TC=32 tokens/block, grid 512, B register-resident (1 float4 per
// expert per thread), unroll 4, streaming STG.128.
// ------------------------------------------------------------------
#define TC 32
__global__ void __launch_bounds__(256) k3_out(const float* __restrict__ lora_B,
                                              float* __restrict__ out) {
    __shared__ float2 cs[TC];
    const int tid = threadIdx.x;
    const int b = blockIdx.x >> 7;                 // 128 blocks per batch
    const int tokbase = (blockIdx.x & 127) * TC;
    const int e0 = g_idx[b * 2], e1 = g_idx[b * 2 + 1];
    const float w0 = g_coef[b * 2], w1 = g_coef[b * 2 + 1];

    if (tid < TC) {
        size_t gt = (size_t)b * SSEQ + tokbase + tid;
        cs[tid] = make_float2(w0 * g_h[gt * EE + e0], w1 * g_h[gt * EE + e1]);
    }
    float4 B0 = *(const float4*)&lora_B[e0 * OUTD + tid * 4];
    float4 B1 = *(const float4*)&lora_B[e1 * OUTD + tid * 4];
    __syncthreads();

    float* ob = out + ((size_t)b * SSEQ + tokbase) * OUTD + tid * 4;
    #pragma unroll 4
    for (int i = 0; i < TC; ++i) {
        float2 cc = cs[i];
        float4 v;
        v.x = cc.x * B0.x + cc.y * B1.x;
        v.y = cc.x * B0.y + cc.y * B1.y;
        v.z = cc.x * B0.z + cc.y * B1.z;
        v.w = cc.x * B0.w + cc.y * B1.w;
        stcs4(ob + (size_t)i * OUTD, v);
    }
}

// ------------------------------------------------------------------
extern "C" void kernel_launch(void* const* d_in, const int* in_sizes, int n_in,
                              void* d_out, int out_size) {
    const float* x      = (const float*)d_in[0];
    const float* lora_A = (const float*)d_in[1];
    const float* lora_B = (const float*)d_in[2];
    const float* gate_w = (const float*)d_in[3];
    const float* gate_b = (const float*)d_in[4];
    float* out = (float*)d_out;

    static bool attr_set = false;
    if (!attr_set) {
        cudaFuncSetAttribute(k1_dots, cudaFuncAttributeMaxDynamicSharedMemorySize, 65536);
        attr_set = true;
    }

    k1_dots<<<BB * (SSEQ / TOKB), 256, 65536>>>(x, lora_A, gate_w, gate_b);
    k3_out<<<BB * (SSEQ / TC), 256>>>(lora_B, out);
}